// round 8
// baseline (speedup 1.0000x reference)
#include <cuda_runtime.h>
#include <cuda_bf16.h>
#include <math.h>
#include <float.h>
#include <stdint.h>

#define Bx 2
#define Tt 2048
#define Dd 2048
#define Nn 16
#define Hh 128
#define WINDOW 1024
#define SOFT_CAP 50.0f

#define SZQ ((size_t)Bx * Nn * Tt * Hh)

// fp32 scratch
__device__ float g_qkv[3ull * Bx * Nn * Tt * Hh];
// bf16 split scratch (GEMMs)
__device__ __nv_bfloat16 g_xhi[(size_t)Bx * Tt * Dd], g_xlo[(size_t)Bx * Tt * Dd];
__device__ __nv_bfloat16 g_wqh[48ull * Hh * Dd],      g_wql[48ull * Hh * Dd];
__device__ __nv_bfloat16 g_woh[(size_t)Dd * Dd],      g_wol[(size_t)Dd * Dd];
__device__ __nv_bfloat16 g_ehi[(size_t)Bx * Tt * Dd], g_elo[(size_t)Bx * Tt * Dd];
// bf16 split scratch (attention): q,k as [b][n][t][h]; v transposed [b][n][h][t]
__device__ __nv_bfloat16 g_qh[SZQ], g_ql[SZQ];
__device__ __nv_bfloat16 g_kh[SZQ], g_kl[SZQ];
__device__ __nv_bfloat16 g_vth[SZQ], g_vtl[SZQ];

// ---------------------------------------------------------------------------
// helpers
// ---------------------------------------------------------------------------
__device__ __forceinline__ uint32_t smem_u32(const void* p) {
    uint32_t a;
    asm("{ .reg .u64 t; cvta.to.shared.u64 t, %1; cvt.u32.u64 %0, t; }" : "=r"(a) : "l"(p));
    return a;
}
__device__ __forceinline__ void ldm4(uint32_t* r, uint32_t addr) {
    asm volatile("ldmatrix.sync.aligned.m8n8.x4.shared.b16 {%0,%1,%2,%3}, [%4];"
        : "=r"(r[0]), "=r"(r[1]), "=r"(r[2]), "=r"(r[3]) : "r"(addr));
}
__device__ __forceinline__ void mma16816(float* c, const uint32_t* a, uint32_t b0, uint32_t b1) {
    asm volatile("mma.sync.aligned.m16n8k16.row.col.f32.bf16.bf16.f32 "
        "{%0,%1,%2,%3}, {%4,%5,%6,%7}, {%8,%9}, {%0,%1,%2,%3};"
        : "+f"(c[0]), "+f"(c[1]), "+f"(c[2]), "+f"(c[3])
        : "r"(a[0]), "r"(a[1]), "r"(a[2]), "r"(a[3]), "r"(b0), "r"(b1));
}
__device__ __forceinline__ void cp16(uint32_t dst, const void* src) {
    asm volatile("cp.async.cg.shared.global [%0], [%1], 16;" :: "r"(dst), "l"(src));
}
#define CP_COMMIT() asm volatile("cp.async.commit_group;" ::: "memory")

// ---------------------------------------------------------------------------
// fp32 -> bf16 hi/lo split (straight)
// ---------------------------------------------------------------------------
__device__ __forceinline__ void split4(const float4 v, __nv_bfloat162* H, __nv_bfloat162* L, size_t i2) {
    __nv_bfloat16 h0 = __float2bfloat16(v.x), h1 = __float2bfloat16(v.y);
    __nv_bfloat16 h2 = __float2bfloat16(v.z), h3 = __float2bfloat16(v.w);
    H[i2]     = __nv_bfloat162(h0, h1);
    H[i2 + 1] = __nv_bfloat162(h2, h3);
    L[i2]     = __nv_bfloat162(__float2bfloat16(v.x - __bfloat162float(h0)),
                               __float2bfloat16(v.y - __bfloat162float(h1)));
    L[i2 + 1] = __nv_bfloat162(__float2bfloat16(v.z - __bfloat162float(h2)),
                               __float2bfloat16(v.w - __bfloat162float(h3)));
}

__global__ void split_x_kernel(const float* __restrict__ in) {
    size_t i = (size_t)blockIdx.x * 256 + threadIdx.x;
    float4 v = ((const float4*)in)[i];
    split4(v, (__nv_bfloat162*)g_xhi, (__nv_bfloat162*)g_xlo, i * 2);
}

// ---------------------------------------------------------------------------
// fp32 [mat][R][C] -> bf16 hi/lo [mat][C][R] transpose split (weights)
// ---------------------------------------------------------------------------
template<int WHICH>
__global__ void transpose_split_kernel(const float* __restrict__ in, int R, int C) {
    __shared__ float tile[32][33];
    const int mat = blockIdx.z;
    const int c0 = blockIdx.x * 32, r0 = blockIdx.y * 32;
    const float* A = in + (size_t)mat * R * C;
    #pragma unroll
    for (int i = threadIdx.y; i < 32; i += 8)
        tile[i][threadIdx.x] = A[(size_t)(r0 + i) * C + c0 + threadIdx.x];
    __syncthreads();
    __nv_bfloat16* H = (WHICH == 0 ? g_wqh : g_woh) + (size_t)mat * R * C;
    __nv_bfloat16* L = (WHICH == 0 ? g_wql : g_wol) + (size_t)mat * R * C;
    #pragma unroll
    for (int i = threadIdx.y; i < 32; i += 8) {
        float v = tile[threadIdx.x][i];
        __nv_bfloat16 h = __float2bfloat16(v);
        size_t o = (size_t)(c0 + i) * R + r0 + threadIdx.x;
        H[o] = h;
        L[o] = __float2bfloat16(v - __bfloat162float(h));
    }
}

// ---------------------------------------------------------------------------
// mma.sync GEMM: 128x128 CTA tile, 4 warps of 64x64 (2x2), K-chunk 32,
// 3-stage cp.async ring, 2 CTAs/SM. Less LDSM duplication (2xA + 2xB).
// ---------------------------------------------------------------------------
#define TILE32_B 8192
#define STAGE32_B (4 * TILE32_B)       // 32 KB
#define GEMM_SMEM (3 * STAGE32_B)      // 96 KB

__device__ __forceinline__ uint32_t sw64(int r, int g) {
    return (uint32_t)(r * 64 + ((g ^ ((r >> 1) & 3)) << 4));
}

template<int MODE>
__global__ void __launch_bounds__(128, 2) mma_gemm(float* __restrict__ outg) {
    extern __shared__ char smc[];
    const uint32_t smb = smem_u32(smc);
    const int tid = threadIdx.x;
    const int wid = tid >> 5, lane = tid & 31;
    const int m0 = blockIdx.x * 128;

    const __nv_bfloat16 *Ahi, *Alo, *Bhi, *Blo;
    if (MODE == 0) { Ahi = g_xhi; Alo = g_xlo; Bhi = g_wqh; Blo = g_wql; }
    else           { Ahi = g_ehi; Alo = g_elo; Bhi = g_woh; Blo = g_wol; }

    // staging: thread tid covers row tid, granules 0..3 (64B row)
    const size_t bbase = (size_t)blockIdx.y * (128 * Dd);
    const __nv_bfloat16* gsrc[4];
    gsrc[0] = Ahi + (size_t)(m0 + tid) * Dd;
    gsrc[1] = Alo + (size_t)(m0 + tid) * Dd;
    gsrc[2] = Bhi + bbase + (size_t)tid * Dd;
    gsrc[3] = Blo + bbase + (size_t)tid * Dd;
    uint32_t soff[4];
    #pragma unroll
    for (int g = 0; g < 4; g++) soff[g] = sw64(tid, g);

    // compute addressing: 2x2 warp grid, 64x64 per warp
    const int wm = wid & 1, wn = wid >> 1;
    const int arow0 = wm * 64 + (lane & 15);
    const int agsel = lane >> 4;
    const int brow0 = wn * 64 + (lane & 7) + (lane >> 4) * 8;
    const int bgsel = (lane >> 3) & 1;

    float acc[4][8][4];
    #pragma unroll
    for (int i = 0; i < 4; i++)
        #pragma unroll
        for (int j = 0; j < 8; j++)
            #pragma unroll
            for (int q = 0; q < 4; q++) acc[i][j][q] = 0.f;

    const int KT = Dd / 32;  // 64 chunks

    #pragma unroll
    for (int pc = 0; pc < 2; pc++) {
        uint32_t buf = smb + pc * STAGE32_B;
        #pragma unroll
        for (int t = 0; t < 4; t++)
            #pragma unroll
            for (int g = 0; g < 4; g++)
                cp16(buf + t * TILE32_B + soff[g], gsrc[t] + pc * 32 + g * 8);
        CP_COMMIT();
    }

    int rbuf = 0, wbuf = 2;
    for (int kc = 0; kc < KT; kc++) {
        if (kc + 1 < KT) asm volatile("cp.async.wait_group 1;" ::: "memory");
        else             asm volatile("cp.async.wait_group 0;" ::: "memory");
        __syncthreads();

        if (kc + 2 < KT) {
            uint32_t buf = smb + wbuf * STAGE32_B;
            #pragma unroll
            for (int t = 0; t < 4; t++)
                #pragma unroll
                for (int g = 0; g < 4; g++)
                    cp16(buf + t * TILE32_B + soff[g], gsrc[t] + (kc + 2) * 32 + g * 8);
            CP_COMMIT();
        }

        const uint32_t tb = smb + rbuf * STAGE32_B;
        #pragma unroll
        for (int ks = 0; ks < 2; ks++) {
            uint32_t ah[4][4], al[4][4];
            #pragma unroll
            for (int mm = 0; mm < 4; mm++) {
                uint32_t ad = sw64(arow0 + mm * 16, ks * 2 + agsel);
                ldm4(ah[mm], tb + ad);
                ldm4(al[mm], tb + TILE32_B + ad);
            }
            #pragma unroll
            for (int jn = 0; jn < 4; jn++) {
                uint32_t bd = sw64(brow0 + jn * 16, ks * 2 + bgsel);
                uint32_t bh[4], bl[4];
                ldm4(bh, tb + 2 * TILE32_B + bd);
                ldm4(bl, tb + 3 * TILE32_B + bd);
                #pragma unroll
                for (int mm = 0; mm < 4; mm++) {
                    mma16816(acc[mm][2 * jn],     ah[mm], bh[0], bh[1]);
                    mma16816(acc[mm][2 * jn + 1], ah[mm], bh[2], bh[3]);
                    mma16816(acc[mm][2 * jn],     al[mm], bh[0], bh[1]);
                    mma16816(acc[mm][2 * jn + 1], al[mm], bh[2], bh[3]);
                    mma16816(acc[mm][2 * jn],     ah[mm], bl[0], bl[1]);
                    mma16816(acc[mm][2 * jn + 1], ah[mm], bl[2], bl[3]);
                }
            }
        }
        rbuf = (rbuf == 2) ? 0 : rbuf + 1;
        wbuf = (wbuf == 2) ? 0 : wbuf + 1;
    }

    // epilogue
    #pragma unroll
    for (int mm = 0; mm < 4; mm++) {
        #pragma unroll
        for (int half = 0; half < 2; half++) {
            const int r = wm * 64 + mm * 16 + (lane >> 2) + half * 8;
            const int m = m0 + r;
            float* rowp;
            if (MODE == 0) {
                const int s = blockIdx.y >> 4, n = blockIdx.y & 15;
                const int b = m >> 11, t = m & (Tt - 1);
                rowp = g_qkv + ((size_t)s * Bx * Nn + (size_t)(b * Nn + n)) * Tt * Hh
                             + (size_t)t * Hh;
            } else {
                rowp = outg + (size_t)m * Dd + blockIdx.y * 128;
            }
            #pragma unroll
            for (int j = 0; j < 8; j++) {
                const int c = wn * 64 + j * 8 + (lane & 3) * 2;
                float2 v;
                v.x = acc[mm][j][half * 2];
                v.y = acc[mm][j][half * 2 + 1];
                *(float2*)(rowp + c) = v;
            }
        }
    }
}

// ---------------------------------------------------------------------------
// RoPE + bf16 split of q (scaled) and k
// ---------------------------------------------------------------------------
__global__ void rope_split_kernel(const int* __restrict__ segment_pos)
{
    const int row = blockIdx.x * 4 + (threadIdx.x >> 6);
    const int h = threadIdx.x & 63;
    const int b = row / (Nn * Tt);
    const int nt = row - b * (Nn * Tt);
    const int n = nt >> 11;
    const int t = nt & (Tt - 1);
    const int pos = segment_pos[b * Tt + t];

    const double ts = pow(10000.0, (double)h / 64.0);
    const float ang = (float)((double)pos / ts);
    float sn, cs;
    sincosf(ang, &sn, &cs);

    const size_t base = ((size_t)(b * Nn + n) * Tt + t) * Hh;
    const float* q = g_qkv + base;
    const float* k = g_qkv + SZQ + base;
    const float qs = 0.08838834764831845f;

    float q1 = q[h], q2 = q[h + 64];
    float qa = (q1 * cs - q2 * sn) * qs;
    float qb = (q2 * cs + q1 * sn) * qs;
    float k1 = k[h], k2 = k[h + 64];
    float ka = k1 * cs - k2 * sn;
    float kb = k2 * cs + k1 * sn;

    __nv_bfloat16 hqa = __float2bfloat16(qa), hqb = __float2bfloat16(qb);
    __nv_bfloat16 hka = __float2bfloat16(ka), hkb = __float2bfloat16(kb);
    g_qh[base + h] = hqa;       g_qh[base + h + 64] = hqb;
    g_ql[base + h] = __float2bfloat16(qa - __bfloat162float(hqa));
    g_ql[base + h + 64] = __float2bfloat16(qb - __bfloat162float(hqb));
    g_kh[base + h] = hka;       g_kh[base + h + 64] = hkb;
    g_kl[base + h] = __float2bfloat16(ka - __bfloat162float(hka));
    g_kl[base + h + 64] = __float2bfloat16(kb - __bfloat162float(hkb));
}

// ---------------------------------------------------------------------------
// V: fp32 [b][n][t][h] -> bf16 hi/lo transposed [b][n][h][t]
// ---------------------------------------------------------------------------
__global__ void vsplit_kernel()
{
    __shared__ float tile[32][33];
    const int bnz = blockIdx.z;
    const int t0 = blockIdx.x * 32, h0 = blockIdx.y * 32;
    const float* v = g_qkv + 2 * SZQ + (size_t)bnz * Tt * Hh;
    #pragma unroll
    for (int i = threadIdx.y; i < 32; i += 8)
        tile[i][threadIdx.x] = v[(size_t)(t0 + i) * Hh + h0 + threadIdx.x];
    __syncthreads();
    const size_t dbase = (size_t)bnz * Hh * Tt;
    #pragma unroll
    for (int i = threadIdx.y; i < 32; i += 8) {
        float val = tile[threadIdx.x][i];
        __nv_bfloat16 hi = __float2bfloat16(val);
        size_t o = dbase + (size_t)(h0 + i) * Tt + t0 + threadIdx.x;
        g_vth[o] = hi;
        g_vtl[o] = __float2bfloat16(val - __bfloat162float(hi));
    }
}

// ---------------------------------------------------------------------------
// Flash attention (R6 config): 128q x 64key chunks, 8 warps, LPT 1D grid
// ---------------------------------------------------------------------------
#define AT_QH 0
#define AT_QL 32768
#define AT_STG 65536
#define AT_STAGE 65536
#define ATTN_SMEM2 (65536 + 2 * 65536)   // 196608

__global__ void __launch_bounds__(256) attn_mma_kernel()
{
    extern __shared__ char smc[];
    const uint32_t smb = smem_u32(smc);
    const int tid = threadIdx.x;
    const int wid = tid >> 5, lane = tid & 31;
    const int qt = 15 - (blockIdx.x >> 5);
    const int sub = blockIdx.x & 31;
    const int n = sub >> 1, b = sub & 1;
    const int t0 = qt * 128;
    const size_t bn = (size_t)(b * Nn + n) * Tt * Hh;

    const __nv_bfloat16* qhp = g_qh + bn;
    const __nv_bfloat16* qlp = g_ql + bn;
    const __nv_bfloat16* khp = g_kh + bn;
    const __nv_bfloat16* klp = g_kl + bn;
    const __nv_bfloat16* vhp = g_vth + bn;
    const __nv_bfloat16* vlp = g_vtl + bn;

    const int c_lo = (t0 >= WINDOW) ? ((t0 - WINDOW + 1) >> 6) : 0;
    const int c_hi = (t0 + 127) >> 6;

    // stage Q
    {
        const int r = tid >> 1;
        const __nv_bfloat16* sh = qhp + (size_t)(t0 + r) * Hh;
        const __nv_bfloat16* sl = qlp + (size_t)(t0 + r) * Hh;
        #pragma unroll
        for (int i = 0; i < 8; i++) {
            int g = (tid & 1) * 8 + i;
            uint32_t off = (uint32_t)(r * 256 + ((g ^ (r & 7)) << 4));
            cp16(smb + AT_QH + off, sh + g * 8);
            cp16(smb + AT_QL + off, sl + g * 8);
        }
        CP_COMMIT();
    }

    // stage chunks c_lo, c_lo+1
    #pragma unroll 1
    for (int pc = 0; pc < 2; pc++) {
        const int c = c_lo + pc;
        const int k0 = c * 64;
        uint32_t sb = smb + AT_STG + (c & 1) * AT_STAGE;
        {
            const int r = tid >> 2;
            const __nv_bfloat16* sh = khp + (size_t)(k0 + r) * Hh;
            const __nv_bfloat16* sl = klp + (size_t)(k0 + r) * Hh;
            #pragma unroll
            for (int i = 0; i < 4; i++) {
                int g = (tid & 3) * 4 + i;
                uint32_t off = (uint32_t)(r * 256 + ((g ^ (r & 7)) << 4));
                cp16(sb + off, sh + g * 8);
                cp16(sb + 16384 + off, sl + g * 8);
            }
        }
        {
            const int r = tid >> 1;
            const __nv_bfloat16* sh = vhp + (size_t)r * Tt + k0;
            const __nv_bfloat16* sl = vlp + (size_t)r * Tt + k0;
            #pragma unroll
            for (int i = 0; i < 4; i++) {
                int g = (tid & 1) * 4 + i;
                uint32_t off = (uint32_t)(r * 128 + ((g ^ (r & 7)) << 4));
                cp16(sb + 32768 + off, sh + g * 8);
                cp16(sb + 49152 + off, sl + g * 8);
            }
        }
        CP_COMMIT();
    }

    float oacc[16][4];
    #pragma unroll
    for (int i = 0; i < 16; i++)
        #pragma unroll
        for (int q = 0; q < 4; q++) oacc[i][q] = 0.f;
    float m0 = -1e30f, m1 = -1e30f, l0 = 0.f, l1 = 0.f;

    const int arow = wid * 16 + (lane & 15);
    const int agsel = lane >> 4;
    const int bro = (lane & 7) + ((lane >> 4) << 3);
    const int bgsel = (lane >> 3) & 1;
    const int qr0 = t0 + wid * 16 + (lane >> 2);

    for (int c = c_lo; c <= c_hi; c++) {
        if (c < c_hi) asm volatile("cp.async.wait_group 1;" ::: "memory");
        else          asm volatile("cp.async.wait_group 0;" ::: "memory");
        __syncthreads();

        const int k0 = c * 64;
        const bool full = (k0 <= t0 - 64) && (k0 >= t0 - (WINDOW - 128));
        const uint32_t KHb = smb + AT_STG + (c & 1) * AT_STAGE;
        const uint32_t KLb = KHb + 16384, VHb = KHb + 32768, VLb = KHb + 49152;

        float sacc[8][4];
        #pragma unroll
        for (int i = 0; i < 8; i++)
            #pragma unroll
            for (int q = 0; q < 4; q++) sacc[i][q] = 0.f;

        #pragma unroll
        for (int ks = 0; ks < 8; ks++) {
            uint32_t qa = (uint32_t)(arow * 256 + (((ks * 2 + agsel) ^ (arow & 7)) << 4));
            uint32_t qhf[4], qlf[4];
            ldm4(qhf, smb + AT_QH + qa);
            ldm4(qlf, smb + AT_QL + qa);
            #pragma unroll
            for (int nk = 0; nk < 4; nk++) {
                int r = nk * 16 + bro;
                uint32_t ka = (uint32_t)(r * 256 + (((ks * 2 + bgsel) ^ (r & 7)) << 4));
                uint32_t khf[4], klf[4];
                ldm4(khf, KHb + ka);
                ldm4(klf, KLb + ka);
                mma16816(sacc[2 * nk],     qhf, khf[0], khf[1]);
                mma16816(sacc[2 * nk + 1], qhf, khf[2], khf[3]);
                mma16816(sacc[2 * nk],     qlf, khf[0], khf[1]);
                mma16816(sacc[2 * nk + 1], qlf, khf[2], khf[3]);
                mma16816(sacc[2 * nk],     qhf, klf[0], klf[1]);
                mma16816(sacc[2 * nk + 1], qhf, klf[2], klf[3]);
            }
        }

        float mx0 = -FLT_MAX, mx1 = -FLT_MAX;
        #pragma unroll
        for (int nt = 0; nt < 8; nt++)
            #pragma unroll
            for (int q = 0; q < 4; q++) {
                float s = sacc[nt][q];
                float e = __expf(s * (2.0f / SOFT_CAP));
                s = SOFT_CAP * (1.f - 2.f / (e + 1.f));
                if (!full) {
                    int qr = qr0 + ((q & 2) ? 8 : 0);
                    int kc = k0 + nt * 8 + (lane & 3) * 2 + (q & 1);
                    if (kc > qr || qr - kc >= WINDOW) s = -FLT_MAX;
                }
                sacc[nt][q] = s;
                if (q & 2) mx1 = fmaxf(mx1, s); else mx0 = fmaxf(mx0, s);
            }
        mx0 = fmaxf(mx0, __shfl_xor_sync(0xffffffffu, mx0, 1));
        mx0 = fmaxf(mx0, __shfl_xor_sync(0xffffffffu, mx0, 2));
        mx1 = fmaxf(mx1, __shfl_xor_sync(0xffffffffu, mx1, 1));
        mx1 = fmaxf(mx1, __shfl_xor_sync(0xffffffffu, mx1, 2));
        float mn0 = fmaxf(m0, mx0), mn1 = fmaxf(m1, mx1);
        float al0 = __expf(m0 - mn0), al1 = __expf(m1 - mn1);
        m0 = mn0; m1 = mn1;
        float s0 = 0.f, s1 = 0.f;
        #pragma unroll
        for (int nt = 0; nt < 8; nt++)
            #pragma unroll
            for (int q = 0; q < 4; q++) {
                float p = __expf(sacc[nt][q] - ((q & 2) ? mn1 : mn0));
                sacc[nt][q] = p;
                if (q & 2) s1 += p; else s0 += p;
            }
        s0 += __shfl_xor_sync(0xffffffffu, s0, 1);
        s0 += __shfl_xor_sync(0xffffffffu, s0, 2);
        s1 += __shfl_xor_sync(0xffffffffu, s1, 1);
        s1 += __shfl_xor_sync(0xffffffffu, s1, 2);
        l0 = l0 * al0 + s0;
        l1 = l1 * al1 + s1;
        #pragma unroll
        for (int i = 0; i < 16; i++) {
            oacc[i][0] *= al0; oacc[i][1] *= al0;
            oacc[i][2] *= al1; oacc[i][3] *= al1;
        }

        uint32_t phi[4][4], plo[4][4];
        #pragma unroll
        for (int kt = 0; kt < 4; kt++) {
            #pragma unroll
            for (int part = 0; part < 4; part++) {
                int nt = 2 * kt + (part >> 1);
                float x = sacc[nt][(part & 1) * 2];
                float y = sacc[nt][(part & 1) * 2 + 1];
                __nv_bfloat162 h2 = __floats2bfloat162_rn(x, y);
                float lx = x - __bfloat162float(h2.x);
                float ly = y - __bfloat162float(h2.y);
                __nv_bfloat162 l2 = __floats2bfloat162_rn(lx, ly);
                phi[kt][part] = *(uint32_t*)&h2;
                plo[kt][part] = *(uint32_t*)&l2;
            }
        }

        #pragma unroll
        for (int kt = 0; kt < 4; kt++) {
            #pragma unroll
            for (int nh = 0; nh < 8; nh++) {
                int r = nh * 16 + bro;
                uint32_t va = (uint32_t)(r * 128 + (((kt * 2 + bgsel) ^ (r & 7)) << 4));
                uint32_t vhf[4], vlf[4];
                ldm4(vhf, VHb + va);
                ldm4(vlf, VLb + va);
                mma16816(oacc[2 * nh],     phi[kt], vhf[0], vhf[1]);
                mma16816(oacc[2 * nh + 1], phi[kt], vhf[2], vhf[3]);
                mma16816(oacc[2 * nh],     plo[kt], vhf[0], vhf[1]);
                mma16816(oacc[2 * nh + 1], plo[kt], vhf[2], vhf[3]);
                mma16816(oacc[2 * nh],     phi[kt], vlf[0], vlf[1]);
                mma16816(oacc[2 * nh + 1], phi[kt], vlf[2], vlf[3]);
            }
        }
        __syncthreads();

        if (c + 2 <= c_hi) {
            const int k2 = (c + 2) * 64;
            uint32_t sb = smb + AT_STG + (c & 1) * AT_STAGE;
            {
                const int r = tid >> 2;
                const __nv_bfloat16* sh = khp + (size_t)(k2 + r) * Hh;
                const __nv_bfloat16* sl = klp + (size_t)(k2 + r) * Hh;
                #pragma unroll
                for (int i = 0; i < 4; i++) {
                    int g = (tid & 3) * 4 + i;
                    uint32_t off = (uint32_t)(r * 256 + ((g ^ (r & 7)) << 4));
                    cp16(sb + off, sh + g * 8);
                    cp16(sb + 16384 + off, sl + g * 8);
                }
            }
            {
                const int r = tid >> 1;
                const __nv_bfloat16* sh = vhp + (size_t)r * Tt + k2;
                const __nv_bfloat16* sl = vlp + (size_t)r * Tt + k2;
                #pragma unroll
                for (int i = 0; i < 4; i++) {
                    int g = (tid & 1) * 4 + i;
                    uint32_t off = (uint32_t)(r * 128 + ((g ^ (r & 7)) << 4));
                    cp16(sb + 32768 + off, sh + g * 8);
                    cp16(sb + 49152 + off, sl + g * 8);
                }
            }
            CP_COMMIT();
        }
    }

    // normalize + hi/lo split + write enc directly as bf16 pair arrays
    float inv0 = 1.f / l0, inv1 = 1.f / l1;
    const int tr0 = t0 + wid * 16 + (lane >> 2);
    #pragma unroll
    for (int nt = 0; nt < 16; nt++) {
        int col = nt * 8 + (lane & 3) * 2;
        size_t o0 = ((size_t)b * Tt + tr0) * Dd + n * Hh + col;
        size_t o1 = ((size_t)b * Tt + tr0 + 8) * Dd + n * Hh + col;
        float x0 = oacc[nt][0] * inv0, y0 = oacc[nt][1] * inv0;
        float x1 = oacc[nt][2] * inv1, y1 = oacc[nt][3] * inv1;
        __nv_bfloat162 h0 = __floats2bfloat162_rn(x0, y0);
        __nv_bfloat162 h1 = __floats2bfloat162_rn(x1, y1);
        __nv_bfloat162 l0v = __floats2bfloat162_rn(x0 - __bfloat162float(h0.x),
                                                   y0 - __bfloat162float(h0.y));
        __nv_bfloat162 l1v = __floats2bfloat162_rn(x1 - __bfloat162float(h1.x),
                                                   y1 - __bfloat162float(h1.y));
        *(__nv_bfloat162*)(g_ehi + o0) = h0;
        *(__nv_bfloat162*)(g_elo + o0) = l0v;
        *(__nv_bfloat162*)(g_ehi + o1) = h1;
        *(__nv_bfloat162*)(g_elo + o1) = l1v;
    }
}

// ---------------------------------------------------------------------------
extern "C" void kernel_launch(void* const* d_in, const int* in_sizes, int n_in,
                              void* d_out, int out_size)
{
    const float* x       = (const float*)d_in[0];
    const float* w_qkv   = (const float*)d_in[1];
    const float* w_out   = (const float*)d_in[2];
    const int*   seg_pos = (const int*)d_in[3];
    float* out = (float*)d_out;

    const int n4 = Bx * Tt * Dd / 4;

    split_x_kernel<<<n4 / 256, 256>>>(x);
    transpose_split_kernel<0><<<dim3(Hh / 32, Dd / 32, 48), dim3(32, 8)>>>(w_qkv, Dd, Hh);
    transpose_split_kernel<1><<<dim3(Dd / 32, Dd / 32, 1), dim3(32, 8)>>>(w_out, Dd, Dd);

    cudaFuncSetAttribute(mma_gemm<0>, cudaFuncAttributeMaxDynamicSharedMemorySize, GEMM_SMEM);
    cudaFuncSetAttribute(mma_gemm<1>, cudaFuncAttributeMaxDynamicSharedMemorySize, GEMM_SMEM);
    cudaFuncSetAttribute(attn_mma_kernel, cudaFuncAttributeMaxDynamicSharedMemorySize, ATTN_SMEM2);

    mma_gemm<0><<<dim3(Bx * Tt / 128, 48), 128, GEMM_SMEM>>>(nullptr);
    rope_split_kernel<<<dim3(Bx * Nn * Tt / 4), 256>>>(seg_pos);
    vsplit_kernel<<<dim3(Tt / 32, Hh / 32, Bx * Nn), dim3(32, 8)>>>();

    attn_mma_kernel<<<dim3(16 * Nn * Bx), 256, ATTN_SMEM2>>>();

    mma_gemm<1><<<dim3(Bx * Tt / 128, Dd / 128), 128, GEMM_SMEM>>>(out);
}

// round 9
// speedup vs baseline: 1.2404x; 1.2404x over previous
#include <cuda_runtime.h>
#include <cuda_bf16.h>
#include <math.h>
#include <float.h>
#include <stdint.h>

#define Bx 2
#define Tt 2048
#define Dd 2048
#define Nn 16
#define Hh 128
#define WINDOW 1024
#define SOFT_CAP 50.0f

#define SZQ ((size_t)Bx * Nn * Tt * Hh)

// fp32 scratch
__device__ float g_qkv[3ull * Bx * Nn * Tt * Hh];
// bf16 split scratch (GEMMs)
__device__ __nv_bfloat16 g_xhi[(size_t)Bx * Tt * Dd], g_xlo[(size_t)Bx * Tt * Dd];
__device__ __nv_bfloat16 g_wqh[48ull * Hh * Dd],      g_wql[48ull * Hh * Dd];
__device__ __nv_bfloat16 g_woh[(size_t)Dd * Dd],      g_wol[(size_t)Dd * Dd];
__device__ __nv_bfloat16 g_ehi[(size_t)Bx * Tt * Dd], g_elo[(size_t)Bx * Tt * Dd];
// bf16 split scratch (attention): q,k as [b][n][t][h]; v transposed [b][n][h][t]
__device__ __nv_bfloat16 g_qh[SZQ], g_ql[SZQ];
__device__ __nv_bfloat16 g_kh[SZQ], g_kl[SZQ];
__device__ __nv_bfloat16 g_vth[SZQ], g_vtl[SZQ];

// ---------------------------------------------------------------------------
// helpers
// ---------------------------------------------------------------------------
__device__ __forceinline__ uint32_t smem_u32(const void* p) {
    uint32_t a;
    asm("{ .reg .u64 t; cvta.to.shared.u64 t, %1; cvt.u32.u64 %0, t; }" : "=r"(a) : "l"(p));
    return a;
}
__device__ __forceinline__ void ldm4(uint32_t* r, uint32_t addr) {
    asm volatile("ldmatrix.sync.aligned.m8n8.x4.shared.b16 {%0,%1,%2,%3}, [%4];"
        : "=r"(r[0]), "=r"(r[1]), "=r"(r[2]), "=r"(r[3]) : "r"(addr));
}
__device__ __forceinline__ void mma16816(float* c, const uint32_t* a, uint32_t b0, uint32_t b1) {
    asm volatile("mma.sync.aligned.m16n8k16.row.col.f32.bf16.bf16.f32 "
        "{%0,%1,%2,%3}, {%4,%5,%6,%7}, {%8,%9}, {%0,%1,%2,%3};"
        : "+f"(c[0]), "+f"(c[1]), "+f"(c[2]), "+f"(c[3])
        : "r"(a[0]), "r"(a[1]), "r"(a[2]), "r"(a[3]), "r"(b0), "r"(b1));
}
__device__ __forceinline__ void cp16(uint32_t dst, const void* src) {
    asm volatile("cp.async.cg.shared.global [%0], [%1], 16;" :: "r"(dst), "l"(src));
}
#define CP_COMMIT() asm volatile("cp.async.commit_group;" ::: "memory")

// ---------------------------------------------------------------------------
// fp32 -> bf16 hi/lo split (straight)
// ---------------------------------------------------------------------------
__device__ __forceinline__ void split4(const float4 v, __nv_bfloat162* H, __nv_bfloat162* L, size_t i2) {
    __nv_bfloat16 h0 = __float2bfloat16(v.x), h1 = __float2bfloat16(v.y);
    __nv_bfloat16 h2 = __float2bfloat16(v.z), h3 = __float2bfloat16(v.w);
    H[i2]     = __nv_bfloat162(h0, h1);
    H[i2 + 1] = __nv_bfloat162(h2, h3);
    L[i2]     = __nv_bfloat162(__float2bfloat16(v.x - __bfloat162float(h0)),
                               __float2bfloat16(v.y - __bfloat162float(h1)));
    L[i2 + 1] = __nv_bfloat162(__float2bfloat16(v.z - __bfloat162float(h2)),
                               __float2bfloat16(v.w - __bfloat162float(h3)));
}

__global__ void split_x_kernel(const float* __restrict__ in) {
    size_t i = (size_t)blockIdx.x * 256 + threadIdx.x;
    float4 v = ((const float4*)in)[i];
    split4(v, (__nv_bfloat162*)g_xhi, (__nv_bfloat162*)g_xlo, i * 2);
}

// ---------------------------------------------------------------------------
// fp32 [mat][R][C] -> bf16 hi/lo [mat][C][R] transpose split (weights)
// ---------------------------------------------------------------------------
template<int WHICH>
__global__ void transpose_split_kernel(const float* __restrict__ in, int R, int C) {
    __shared__ float tile[32][33];
    const int mat = blockIdx.z;
    const int c0 = blockIdx.x * 32, r0 = blockIdx.y * 32;
    const float* A = in + (size_t)mat * R * C;
    #pragma unroll
    for (int i = threadIdx.y; i < 32; i += 8)
        tile[i][threadIdx.x] = A[(size_t)(r0 + i) * C + c0 + threadIdx.x];
    __syncthreads();
    __nv_bfloat16* H = (WHICH == 0 ? g_wqh : g_woh) + (size_t)mat * R * C;
    __nv_bfloat16* L = (WHICH == 0 ? g_wql : g_wol) + (size_t)mat * R * C;
    #pragma unroll
    for (int i = threadIdx.y; i < 32; i += 8) {
        float v = tile[threadIdx.x][i];
        __nv_bfloat16 h = __float2bfloat16(v);
        size_t o = (size_t)(c0 + i) * R + r0 + threadIdx.x;
        H[o] = h;
        L[o] = __float2bfloat16(v - __bfloat162float(h));
    }
}

// ---------------------------------------------------------------------------
// mma.sync GEMM (R6 config): K-chunk 32, 3-stage ring, 256 thr, 2 CTAs/SM
// ---------------------------------------------------------------------------
#define TILE32_B 8192
#define STAGE32_B (4 * TILE32_B)       // 32 KB
#define GEMM_SMEM (3 * STAGE32_B)      // 96 KB

__device__ __forceinline__ uint32_t sw64(int r, int g) {
    return (uint32_t)(r * 64 + ((g ^ ((r >> 1) & 3)) << 4));
}

template<int MODE>
__global__ void __launch_bounds__(256, 2) mma_gemm(float* __restrict__ outg) {
    extern __shared__ char smc[];
    const uint32_t smb = smem_u32(smc);
    const int tid = threadIdx.x;
    const int wid = tid >> 5, lane = tid & 31;
    const int m0 = blockIdx.x * 128;

    const __nv_bfloat16 *Ahi, *Alo, *Bhi, *Blo;
    if (MODE == 0) { Ahi = g_xhi; Alo = g_xlo; Bhi = g_wqh; Blo = g_wql; }
    else           { Ahi = g_ehi; Alo = g_elo; Bhi = g_woh; Blo = g_wol; }

    const int srow = tid >> 1, sg0 = (tid & 1) * 2;
    const size_t bbase = (size_t)blockIdx.y * (128 * Dd);
    const __nv_bfloat16* gsrc[4];
    gsrc[0] = Ahi + (size_t)(m0 + srow) * Dd + sg0 * 8;
    gsrc[1] = Alo + (size_t)(m0 + srow) * Dd + sg0 * 8;
    gsrc[2] = Bhi + bbase + (size_t)srow * Dd + sg0 * 8;
    gsrc[3] = Blo + bbase + (size_t)srow * Dd + sg0 * 8;
    uint32_t soff[2];
    soff[0] = sw64(srow, sg0);
    soff[1] = sw64(srow, sg0 + 1);

    const int wm = wid & 3, wn = wid >> 2;
    const int arow = wm * 32 + (lane & 15);
    const int agsel = lane >> 4;
    const int brow = wn * 64 + (lane & 7) + (lane >> 4) * 8;
    const int bgsel = (lane >> 3) & 1;

    float acc[2][8][4];
    #pragma unroll
    for (int i = 0; i < 2; i++)
        #pragma unroll
        for (int j = 0; j < 8; j++)
            #pragma unroll
            for (int q = 0; q < 4; q++) acc[i][j][q] = 0.f;

    const int KT = Dd / 32;  // 64 chunks

    #pragma unroll
    for (int pc = 0; pc < 2; pc++) {
        uint32_t buf = smb + pc * STAGE32_B;
        #pragma unroll
        for (int t = 0; t < 4; t++) {
            cp16(buf + t * TILE32_B + soff[0], gsrc[t] + pc * 32);
            cp16(buf + t * TILE32_B + soff[1], gsrc[t] + pc * 32 + 8);
        }
        CP_COMMIT();
    }

    int rbuf = 0, wbuf = 2;
    for (int kc = 0; kc < KT; kc++) {
        if (kc + 1 < KT) asm volatile("cp.async.wait_group 1;" ::: "memory");
        else             asm volatile("cp.async.wait_group 0;" ::: "memory");
        __syncthreads();

        if (kc + 2 < KT) {
            uint32_t buf = smb + wbuf * STAGE32_B;
            #pragma unroll
            for (int t = 0; t < 4; t++) {
                cp16(buf + t * TILE32_B + soff[0], gsrc[t] + (kc + 2) * 32);
                cp16(buf + t * TILE32_B + soff[1], gsrc[t] + (kc + 2) * 32 + 8);
            }
            CP_COMMIT();
        }

        const uint32_t tb = smb + rbuf * STAGE32_B;
        #pragma unroll
        for (int ks = 0; ks < 2; ks++) {
            uint32_t ah[2][4], al[2][4];
            #pragma unroll
            for (int mm = 0; mm < 2; mm++) {
                uint32_t ad = sw64(arow + mm * 16, ks * 2 + agsel);
                ldm4(ah[mm], tb + ad);
                ldm4(al[mm], tb + TILE32_B + ad);
            }
            #pragma unroll
            for (int j = 0; j < 4; j++) {
                uint32_t bd = sw64(brow + j * 16, ks * 2 + bgsel);
                uint32_t bh[4], bl[4];
                ldm4(bh, tb + 2 * TILE32_B + bd);
                ldm4(bl, tb + 3 * TILE32_B + bd);
                mma16816(acc[0][2 * j],     ah[0], bh[0], bh[1]);
                mma16816(acc[0][2 * j + 1], ah[0], bh[2], bh[3]);
                mma16816(acc[1][2 * j],     ah[1], bh[0], bh[1]);
                mma16816(acc[1][2 * j + 1], ah[1], bh[2], bh[3]);
                mma16816(acc[0][2 * j],     al[0], bh[0], bh[1]);
                mma16816(acc[0][2 * j + 1], al[0], bh[2], bh[3]);
                mma16816(acc[1][2 * j],     al[1], bh[0], bh[1]);
                mma16816(acc[1][2 * j + 1], al[1], bh[2], bh[3]);
                mma16816(acc[0][2 * j],     ah[0], bl[0], bl[1]);
                mma16816(acc[0][2 * j + 1], ah[0], bl[2], bl[3]);
                mma16816(acc[1][2 * j],     ah[1], bl[0], bl[1]);
                mma16816(acc[1][2 * j + 1], ah[1], bl[2], bl[3]);
            }
        }
        rbuf = (rbuf == 2) ? 0 : rbuf + 1;
        wbuf = (wbuf == 2) ? 0 : wbuf + 1;
    }

    #pragma unroll
    for (int mm = 0; mm < 2; mm++) {
        #pragma unroll
        for (int half = 0; half < 2; half++) {
            const int r = wm * 32 + mm * 16 + (lane >> 2) + half * 8;
            const int m = m0 + r;
            float* rowp;
            if (MODE == 0) {
                const int s = blockIdx.y >> 4, n = blockIdx.y & 15;
                const int b = m >> 11, t = m & (Tt - 1);
                rowp = g_qkv + ((size_t)s * Bx * Nn + (size_t)(b * Nn + n)) * Tt * Hh
                             + (size_t)t * Hh;
            } else {
                rowp = outg + (size_t)m * Dd + blockIdx.y * 128;
            }
            #pragma unroll
            for (int j = 0; j < 8; j++) {
                const int c = wn * 64 + j * 8 + (lane & 3) * 2;
                float2 v;
                v.x = acc[mm][j][half * 2];
                v.y = acc[mm][j][half * 2 + 1];
                *(float2*)(rowp + c) = v;
            }
        }
    }
}

// ---------------------------------------------------------------------------
// RoPE + bf16 split of q (scaled) and k
// ---------------------------------------------------------------------------
__global__ void rope_split_kernel(const int* __restrict__ segment_pos)
{
    const int row = blockIdx.x * 4 + (threadIdx.x >> 6);
    const int h = threadIdx.x & 63;
    const int b = row / (Nn * Tt);
    const int nt = row - b * (Nn * Tt);
    const int n = nt >> 11;
    const int t = nt & (Tt - 1);
    const int pos = segment_pos[b * Tt + t];

    const double ts = pow(10000.0, (double)h / 64.0);
    const float ang = (float)((double)pos / ts);
    float sn, cs;
    sincosf(ang, &sn, &cs);

    const size_t base = ((size_t)(b * Nn + n) * Tt + t) * Hh;
    const float* q = g_qkv + base;
    const float* k = g_qkv + SZQ + base;
    const float qs = 0.08838834764831845f;

    float q1 = q[h], q2 = q[h + 64];
    float qa = (q1 * cs - q2 * sn) * qs;
    float qb = (q2 * cs + q1 * sn) * qs;
    float k1 = k[h], k2 = k[h + 64];
    float ka = k1 * cs - k2 * sn;
    float kb = k2 * cs + k1 * sn;

    __nv_bfloat16 hqa = __float2bfloat16(qa), hqb = __float2bfloat16(qb);
    __nv_bfloat16 hka = __float2bfloat16(ka), hkb = __float2bfloat16(kb);
    g_qh[base + h] = hqa;       g_qh[base + h + 64] = hqb;
    g_ql[base + h] = __float2bfloat16(qa - __bfloat162float(hqa));
    g_ql[base + h + 64] = __float2bfloat16(qb - __bfloat162float(hqb));
    g_kh[base + h] = hka;       g_kh[base + h + 64] = hkb;
    g_kl[base + h] = __float2bfloat16(ka - __bfloat162float(hka));
    g_kl[base + h + 64] = __float2bfloat16(kb - __bfloat162float(hkb));
}

// ---------------------------------------------------------------------------
// V: fp32 [b][n][t][h] -> bf16 hi/lo transposed [b][n][h][t]
// ---------------------------------------------------------------------------
__global__ void vsplit_kernel()
{
    __shared__ float tile[32][33];
    const int bnz = blockIdx.z;
    const int t0 = blockIdx.x * 32, h0 = blockIdx.y * 32;
    const float* v = g_qkv + 2 * SZQ + (size_t)bnz * Tt * Hh;
    #pragma unroll
    for (int i = threadIdx.y; i < 32; i += 8)
        tile[i][threadIdx.x] = v[(size_t)(t0 + i) * Hh + h0 + threadIdx.x];
    __syncthreads();
    const size_t dbase = (size_t)bnz * Hh * Tt;
    #pragma unroll
    for (int i = threadIdx.y; i < 32; i += 8) {
        float val = tile[threadIdx.x][i];
        __nv_bfloat16 hi = __float2bfloat16(val);
        size_t o = dbase + (size_t)(h0 + i) * Tt + t0 + threadIdx.x;
        g_vth[o] = hi;
        g_vtl[o] = __float2bfloat16(val - __bfloat162float(hi));
    }
}

// ---------------------------------------------------------------------------
// Flash attention (R6 tiles) with fixed-base softmax (m == 0):
// logits bounded in [-50, 50] by the soft cap, so exp(s) never over/underflows.
// No online max, no alpha rescale. Mask sets p = 0 directly.
// ---------------------------------------------------------------------------
#define AT_QH 0
#define AT_QL 32768
#define AT_STG 65536
#define AT_STAGE 65536
#define ATTN_SMEM2 (65536 + 2 * 65536)   // 196608

__global__ void __launch_bounds__(256) attn_mma_kernel()
{
    extern __shared__ char smc[];
    const uint32_t smb = smem_u32(smc);
    const int tid = threadIdx.x;
    const int wid = tid >> 5, lane = tid & 31;
    const int qt = 15 - (blockIdx.x >> 5);
    const int sub = blockIdx.x & 31;
    const int n = sub >> 1, b = sub & 1;
    const int t0 = qt * 128;
    const size_t bn = (size_t)(b * Nn + n) * Tt * Hh;

    const __nv_bfloat16* qhp = g_qh + bn;
    const __nv_bfloat16* qlp = g_ql + bn;
    const __nv_bfloat16* khp = g_kh + bn;
    const __nv_bfloat16* klp = g_kl + bn;
    const __nv_bfloat16* vhp = g_vth + bn;
    const __nv_bfloat16* vlp = g_vtl + bn;

    const int c_lo = (t0 >= WINDOW) ? ((t0 - WINDOW + 1) >> 6) : 0;
    const int c_hi = (t0 + 127) >> 6;

    // stage Q
    {
        const int r = tid >> 1;
        const __nv_bfloat16* sh = qhp + (size_t)(t0 + r) * Hh;
        const __nv_bfloat16* sl = qlp + (size_t)(t0 + r) * Hh;
        #pragma unroll
        for (int i = 0; i < 8; i++) {
            int g = (tid & 1) * 8 + i;
            uint32_t off = (uint32_t)(r * 256 + ((g ^ (r & 7)) << 4));
            cp16(smb + AT_QH + off, sh + g * 8);
            cp16(smb + AT_QL + off, sl + g * 8);
        }
        CP_COMMIT();
    }

    // stage chunks c_lo, c_lo+1
    #pragma unroll 1
    for (int pc = 0; pc < 2; pc++) {
        const int c = c_lo + pc;
        const int k0 = c * 64;
        uint32_t sb = smb + AT_STG + (c & 1) * AT_STAGE;
        {
            const int r = tid >> 2;
            const __nv_bfloat16* sh = khp + (size_t)(k0 + r) * Hh;
            const __nv_bfloat16* sl = klp + (size_t)(k0 + r) * Hh;
            #pragma unroll
            for (int i = 0; i < 4; i++) {
                int g = (tid & 3) * 4 + i;
                uint32_t off = (uint32_t)(r * 256 + ((g ^ (r & 7)) << 4));
                cp16(sb + off, sh + g * 8);
                cp16(sb + 16384 + off, sl + g * 8);
            }
        }
        {
            const int r = tid >> 1;
            const __nv_bfloat16* sh = vhp + (size_t)r * Tt + k0;
            const __nv_bfloat16* sl = vlp + (size_t)r * Tt + k0;
            #pragma unroll
            for (int i = 0; i < 4; i++) {
                int g = (tid & 1) * 4 + i;
                uint32_t off = (uint32_t)(r * 128 + ((g ^ (r & 7)) << 4));
                cp16(sb + 32768 + off, sh + g * 8);
                cp16(sb + 49152 + off, sl + g * 8);
            }
        }
        CP_COMMIT();
    }

    float oacc[16][4];
    #pragma unroll
    for (int i = 0; i < 16; i++)
        #pragma unroll
        for (int q = 0; q < 4; q++) oacc[i][q] = 0.f;
    float l0 = 0.f, l1 = 0.f;

    const int arow = wid * 16 + (lane & 15);
    const int agsel = lane >> 4;
    const int bro = (lane & 7) + ((lane >> 4) << 3);
    const int bgsel = (lane >> 3) & 1;
    const int qr0 = t0 + wid * 16 + (lane >> 2);

    for (int c = c_lo; c <= c_hi; c++) {
        if (c < c_hi) asm volatile("cp.async.wait_group 1;" ::: "memory");
        else          asm volatile("cp.async.wait_group 0;" ::: "memory");
        __syncthreads();

        const int k0 = c * 64;
        const bool full = (k0 <= t0 - 64) && (k0 >= t0 - (WINDOW - 128));
        const uint32_t KHb = smb + AT_STG + (c & 1) * AT_STAGE;
        const uint32_t KLb = KHb + 16384, VHb = KHb + 32768, VLb = KHb + 49152;

        float sacc[8][4];
        #pragma unroll
        for (int i = 0; i < 8; i++)
            #pragma unroll
            for (int q = 0; q < 4; q++) sacc[i][q] = 0.f;

        #pragma unroll
        for (int ks = 0; ks < 8; ks++) {
            uint32_t qa = (uint32_t)(arow * 256 + (((ks * 2 + agsel) ^ (arow & 7)) << 4));
            uint32_t qhf[4], qlf[4];
            ldm4(qhf, smb + AT_QH + qa);
            ldm4(qlf, smb + AT_QL + qa);
            #pragma unroll
            for (int nk = 0; nk < 4; nk++) {
                int r = nk * 16 + bro;
                uint32_t ka = (uint32_t)(r * 256 + (((ks * 2 + bgsel) ^ (r & 7)) << 4));
                uint32_t khf[4], klf[4];
                ldm4(khf, KHb + ka);
                ldm4(klf, KLb + ka);
                mma16816(sacc[2 * nk],     qhf, khf[0], khf[1]);
                mma16816(sacc[2 * nk + 1], qhf, khf[2], khf[3]);
                mma16816(sacc[2 * nk],     qlf, khf[0], khf[1]);
                mma16816(sacc[2 * nk + 1], qlf, khf[2], khf[3]);
                mma16816(sacc[2 * nk],     qhf, klf[0], klf[1]);
                mma16816(sacc[2 * nk + 1], qhf, klf[2], klf[3]);
            }
        }

        // softcap + mask + exp with fixed base (no max needed: |logit| <= 50)
        float s0 = 0.f, s1 = 0.f;
        #pragma unroll
        for (int nt = 0; nt < 8; nt++)
            #pragma unroll
            for (int q = 0; q < 4; q++) {
                float s = sacc[nt][q];
                float e = __expf(s * (2.0f / SOFT_CAP));
                float r = __fdividef(2.0f, e + 1.0f);
                float p = __expf(SOFT_CAP - SOFT_CAP * r);
                if (!full) {
                    int qr = qr0 + ((q & 2) ? 8 : 0);
                    int kc = k0 + nt * 8 + (lane & 3) * 2 + (q & 1);
                    if (kc > qr || qr - kc >= WINDOW) p = 0.f;
                }
                sacc[nt][q] = p;
                if (q & 2) s1 += p; else s0 += p;
            }
        s0 += __shfl_xor_sync(0xffffffffu, s0, 1);
        s0 += __shfl_xor_sync(0xffffffffu, s0, 2);
        s1 += __shfl_xor_sync(0xffffffffu, s1, 1);
        s1 += __shfl_xor_sync(0xffffffffu, s1, 2);
        l0 += s0;
        l1 += s1;

        uint32_t phi[4][4], plo[4][4];
        #pragma unroll
        for (int kt = 0; kt < 4; kt++) {
            #pragma unroll
            for (int part = 0; part < 4; part++) {
                int nt = 2 * kt + (part >> 1);
                float x = sacc[nt][(part & 1) * 2];
                float y = sacc[nt][(part & 1) * 2 + 1];
                __nv_bfloat162 h2 = __floats2bfloat162_rn(x, y);
                float lx = x - __bfloat162float(h2.x);
                float ly = y - __bfloat162float(h2.y);
                __nv_bfloat162 l2 = __floats2bfloat162_rn(lx, ly);
                phi[kt][part] = *(uint32_t*)&h2;
                plo[kt][part] = *(uint32_t*)&l2;
            }
        }

        #pragma unroll
        for (int kt = 0; kt < 4; kt++) {
            #pragma unroll
            for (int nh = 0; nh < 8; nh++) {
                int r = nh * 16 + bro;
                uint32_t va = (uint32_t)(r * 128 + (((kt * 2 + bgsel) ^ (r & 7)) << 4));
                uint32_t vhf[4], vlf[4];
                ldm4(vhf, VHb + va);
                ldm4(vlf, VLb + va);
                mma16816(oacc[2 * nh],     phi[kt], vhf[0], vhf[1]);
                mma16816(oacc[2 * nh + 1], phi[kt], vhf[2], vhf[3]);
                mma16816(oacc[2 * nh],     plo[kt], vhf[0], vhf[1]);
                mma16816(oacc[2 * nh + 1], plo[kt], vhf[2], vhf[3]);
                mma16816(oacc[2 * nh],     phi[kt], vlf[0], vlf[1]);
                mma16816(oacc[2 * nh + 1], phi[kt], vlf[2], vlf[3]);
            }
        }
        __syncthreads();

        if (c + 2 <= c_hi) {
            const int k2 = (c + 2) * 64;
            uint32_t sb = smb + AT_STG + (c & 1) * AT_STAGE;
            {
                const int r = tid >> 2;
                const __nv_bfloat16* sh = khp + (size_t)(k2 + r) * Hh;
                const __nv_bfloat16* sl = klp + (size_t)(k2 + r) * Hh;
                #pragma unroll
                for (int i = 0; i < 4; i++) {
                    int g = (tid & 3) * 4 + i;
                    uint32_t off = (uint32_t)(r * 256 + ((g ^ (r & 7)) << 4));
                    cp16(sb + off, sh + g * 8);
                    cp16(sb + 16384 + off, sl + g * 8);
                }
            }
            {
                const int r = tid >> 1;
                const __nv_bfloat16* sh = vhp + (size_t)r * Tt + k2;
                const __nv_bfloat16* sl = vlp + (size_t)r * Tt + k2;
                #pragma unroll
                for (int i = 0; i < 4; i++) {
                    int g = (tid & 1) * 4 + i;
                    uint32_t off = (uint32_t)(r * 128 + ((g ^ (r & 7)) << 4));
                    cp16(sb + 32768 + off, sh + g * 8);
                    cp16(sb + 49152 + off, sl + g * 8);
                }
            }
            CP_COMMIT();
        }
    }

    // normalize + hi/lo split + write enc directly as bf16 pair arrays
    float inv0 = __fdividef(1.f, l0), inv1 = __fdividef(1.f, l1);
    const int tr0 = t0 + wid * 16 + (lane >> 2);
    #pragma unroll
    for (int nt = 0; nt < 16; nt++) {
        int col = nt * 8 + (lane & 3) * 2;
        size_t o0 = ((size_t)b * Tt + tr0) * Dd + n * Hh + col;
        size_t o1 = ((size_t)b * Tt + tr0 + 8) * Dd + n * Hh + col;
        float x0 = oacc[nt][0] * inv0, y0 = oacc[nt][1] * inv0;
        float x1 = oacc[nt][2] * inv1, y1 = oacc[nt][3] * inv1;
        __nv_bfloat162 h0 = __floats2bfloat162_rn(x0, y0);
        __nv_bfloat162 h1 = __floats2bfloat162_rn(x1, y1);
        __nv_bfloat162 l0v = __floats2bfloat162_rn(x0 - __bfloat162float(h0.x),
                                                   y0 - __bfloat162float(h0.y));
        __nv_bfloat162 l1v = __floats2bfloat162_rn(x1 - __bfloat162float(h1.x),
                                                   y1 - __bfloat162float(h1.y));
        *(__nv_bfloat162*)(g_ehi + o0) = h0;
        *(__nv_bfloat162*)(g_elo + o0) = l0v;
        *(__nv_bfloat162*)(g_ehi + o1) = h1;
        *(__nv_bfloat162*)(g_elo + o1) = l1v;
    }
}

// ---------------------------------------------------------------------------
extern "C" void kernel_launch(void* const* d_in, const int* in_sizes, int n_in,
                              void* d_out, int out_size)
{
    const float* x       = (const float*)d_in[0];
    const float* w_qkv   = (const float*)d_in[1];
    const float* w_out   = (const float*)d_in[2];
    const int*   seg_pos = (const int*)d_in[3];
    float* out = (float*)d_out;

    const int n4 = Bx * Tt * Dd / 4;

    split_x_kernel<<<n4 / 256, 256>>>(x);
    transpose_split_kernel<0><<<dim3(Hh / 32, Dd / 32, 48), dim3(32, 8)>>>(w_qkv, Dd, Hh);
    transpose_split_kernel<1><<<dim3(Dd / 32, Dd / 32, 1), dim3(32, 8)>>>(w_out, Dd, Dd);

    cudaFuncSetAttribute(mma_gemm<0>, cudaFuncAttributeMaxDynamicSharedMemorySize, GEMM_SMEM);
    cudaFuncSetAttribute(mma_gemm<1>, cudaFuncAttributeMaxDynamicSharedMemorySize, GEMM_SMEM);
    cudaFuncSetAttribute(attn_mma_kernel, cudaFuncAttributeMaxDynamicSharedMemorySize, ATTN_SMEM2);

    mma_gemm<0><<<dim3(Bx * Tt / 128, 48), 256, GEMM_SMEM>>>(nullptr);
    rope_split_kernel<<<dim3(Bx * Nn * Tt / 4), 256>>>(seg_pos);
    vsplit_kernel<<<dim3(Tt / 32, Hh / 32, Bx * Nn), dim3(32, 8)>>>();

    attn_mma_kernel<<<dim3(16 * Nn * Bx), 256, ATTN_SMEM2>>>();

    mma_gemm<1><<<dim3(Bx * Tt / 128, Dd / 128), 256, GEMM_SMEM>>>(out);
}

// round 10
// speedup vs baseline: 1.2543x; 1.0112x over previous
#include <cuda_runtime.h>
#include <cuda_bf16.h>
#include <math.h>
#include <float.h>
#include <stdint.h>

#define Bx 2
#define Tt 2048
#define Dd 2048
#define Nn 16
#define Hh 128
#define WINDOW 1024
#define SOFT_CAP 50.0f

#define SZQ ((size_t)Bx * Nn * Tt * Hh)

// fp32 scratch
__device__ float g_qkv[3ull * Bx * Nn * Tt * Hh];
// bf16 split scratch (GEMMs)
__device__ __nv_bfloat16 g_xhi[(size_t)Bx * Tt * Dd], g_xlo[(size_t)Bx * Tt * Dd];
__device__ __nv_bfloat16 g_wqh[48ull * Hh * Dd],      g_wql[48ull * Hh * Dd];
__device__ __nv_bfloat16 g_woh[(size_t)Dd * Dd],      g_wol[(size_t)Dd * Dd];
__device__ __nv_bfloat16 g_ehi[(size_t)Bx * Tt * Dd], g_elo[(size_t)Bx * Tt * Dd];
// bf16 split scratch (attention): q,k as [b][n][t][h]; v transposed [b][n][h][t]
__device__ __nv_bfloat16 g_qh[SZQ], g_ql[SZQ];
__device__ __nv_bfloat16 g_kh[SZQ], g_kl[SZQ];
__device__ __nv_bfloat16 g_vth[SZQ], g_vtl[SZQ];

// ---------------------------------------------------------------------------
// helpers
// ---------------------------------------------------------------------------
__device__ __forceinline__ uint32_t smem_u32(const void* p) {
    uint32_t a;
    asm("{ .reg .u64 t; cvta.to.shared.u64 t, %1; cvt.u32.u64 %0, t; }" : "=r"(a) : "l"(p));
    return a;
}
__device__ __forceinline__ void ldm4(uint32_t* r, uint32_t addr) {
    asm volatile("ldmatrix.sync.aligned.m8n8.x4.shared.b16 {%0,%1,%2,%3}, [%4];"
        : "=r"(r[0]), "=r"(r[1]), "=r"(r[2]), "=r"(r[3]) : "r"(addr));
}
__device__ __forceinline__ void mma16816(float* c, const uint32_t* a, uint32_t b0, uint32_t b1) {
    asm volatile("mma.sync.aligned.m16n8k16.row.col.f32.bf16.bf16.f32 "
        "{%0,%1,%2,%3}, {%4,%5,%6,%7}, {%8,%9}, {%0,%1,%2,%3};"
        : "+f"(c[0]), "+f"(c[1]), "+f"(c[2]), "+f"(c[3])
        : "r"(a[0]), "r"(a[1]), "r"(a[2]), "r"(a[3]), "r"(b0), "r"(b1));
}
__device__ __forceinline__ void cp16(uint32_t dst, const void* src) {
    asm volatile("cp.async.cg.shared.global [%0], [%1], 16;" :: "r"(dst), "l"(src));
}
#define CP_COMMIT() asm volatile("cp.async.commit_group;" ::: "memory")

// ---------------------------------------------------------------------------
// fp32 -> bf16 hi/lo split (straight)
// ---------------------------------------------------------------------------
__device__ __forceinline__ void split4(const float4 v, __nv_bfloat162* H, __nv_bfloat162* L, size_t i2) {
    __nv_bfloat16 h0 = __float2bfloat16(v.x), h1 = __float2bfloat16(v.y);
    __nv_bfloat16 h2 = __float2bfloat16(v.z), h3 = __float2bfloat16(v.w);
    H[i2]     = __nv_bfloat162(h0, h1);
    H[i2 + 1] = __nv_bfloat162(h2, h3);
    L[i2]     = __nv_bfloat162(__float2bfloat16(v.x - __bfloat162float(h0)),
                               __float2bfloat16(v.y - __bfloat162float(h1)));
    L[i2 + 1] = __nv_bfloat162(__float2bfloat16(v.z - __bfloat162float(h2)),
                               __float2bfloat16(v.w - __bfloat162float(h3)));
}

__global__ void split_x_kernel(const float* __restrict__ in) {
    size_t i = (size_t)blockIdx.x * 256 + threadIdx.x;
    float4 v = ((const float4*)in)[i];
    split4(v, (__nv_bfloat162*)g_xhi, (__nv_bfloat162*)g_xlo, i * 2);
}

// ---------------------------------------------------------------------------
// fp32 [mat][R][C] -> bf16 hi/lo [mat][C][R] transpose split (weights)
// ---------------------------------------------------------------------------
template<int WHICH>
__global__ void transpose_split_kernel(const float* __restrict__ in, int R, int C) {
    __shared__ float tile[32][33];
    const int mat = blockIdx.z;
    const int c0 = blockIdx.x * 32, r0 = blockIdx.y * 32;
    const float* A = in + (size_t)mat * R * C;
    #pragma unroll
    for (int i = threadIdx.y; i < 32; i += 8)
        tile[i][threadIdx.x] = A[(size_t)(r0 + i) * C + c0 + threadIdx.x];
    __syncthreads();
    __nv_bfloat16* H = (WHICH == 0 ? g_wqh : g_woh) + (size_t)mat * R * C;
    __nv_bfloat16* L = (WHICH == 0 ? g_wql : g_wol) + (size_t)mat * R * C;
    #pragma unroll
    for (int i = threadIdx.y; i < 32; i += 8) {
        float v = tile[threadIdx.x][i];
        __nv_bfloat16 h = __float2bfloat16(v);
        size_t o = (size_t)(c0 + i) * R + r0 + threadIdx.x;
        H[o] = h;
        L[o] = __float2bfloat16(v - __bfloat162float(h));
    }
}

// ---------------------------------------------------------------------------
// mma.sync GEMM (R6 config): K-chunk 32, 3-stage ring, 256 thr, 2 CTAs/SM
// ---------------------------------------------------------------------------
#define TILE32_B 8192
#define STAGE32_B (4 * TILE32_B)       // 32 KB
#define GEMM_SMEM (3 * STAGE32_B)      // 96 KB

__device__ __forceinline__ uint32_t sw64(int r, int g) {
    return (uint32_t)(r * 64 + ((g ^ ((r >> 1) & 3)) << 4));
}

template<int MODE>
__global__ void __launch_bounds__(256, 2) mma_gemm(float* __restrict__ outg) {
    extern __shared__ char smc[];
    const uint32_t smb = smem_u32(smc);
    const int tid = threadIdx.x;
    const int wid = tid >> 5, lane = tid & 31;
    const int m0 = blockIdx.x * 128;

    const __nv_bfloat16 *Ahi, *Alo, *Bhi, *Blo;
    if (MODE == 0) { Ahi = g_xhi; Alo = g_xlo; Bhi = g_wqh; Blo = g_wql; }
    else           { Ahi = g_ehi; Alo = g_elo; Bhi = g_woh; Blo = g_wol; }

    const int srow = tid >> 1, sg0 = (tid & 1) * 2;
    const size_t bbase = (size_t)blockIdx.y * (128 * Dd);
    const __nv_bfloat16* gsrc[4];
    gsrc[0] = Ahi + (size_t)(m0 + srow) * Dd + sg0 * 8;
    gsrc[1] = Alo + (size_t)(m0 + srow) * Dd + sg0 * 8;
    gsrc[2] = Bhi + bbase + (size_t)srow * Dd + sg0 * 8;
    gsrc[3] = Blo + bbase + (size_t)srow * Dd + sg0 * 8;
    uint32_t soff[2];
    soff[0] = sw64(srow, sg0);
    soff[1] = sw64(srow, sg0 + 1);

    const int wm = wid & 3, wn = wid >> 2;
    const int arow = wm * 32 + (lane & 15);
    const int agsel = lane >> 4;
    const int brow = wn * 64 + (lane & 7) + (lane >> 4) * 8;
    const int bgsel = (lane >> 3) & 1;

    float acc[2][8][4];
    #pragma unroll
    for (int i = 0; i < 2; i++)
        #pragma unroll
        for (int j = 0; j < 8; j++)
            #pragma unroll
            for (int q = 0; q < 4; q++) acc[i][j][q] = 0.f;

    const int KT = Dd / 32;  // 64 chunks

    #pragma unroll
    for (int pc = 0; pc < 2; pc++) {
        uint32_t buf = smb + pc * STAGE32_B;
        #pragma unroll
        for (int t = 0; t < 4; t++) {
            cp16(buf + t * TILE32_B + soff[0], gsrc[t] + pc * 32);
            cp16(buf + t * TILE32_B + soff[1], gsrc[t] + pc * 32 + 8);
        }
        CP_COMMIT();
    }

    int rbuf = 0, wbuf = 2;
    for (int kc = 0; kc < KT; kc++) {
        if (kc + 1 < KT) asm volatile("cp.async.wait_group 1;" ::: "memory");
        else             asm volatile("cp.async.wait_group 0;" ::: "memory");
        __syncthreads();

        if (kc + 2 < KT) {
            uint32_t buf = smb + wbuf * STAGE32_B;
            #pragma unroll
            for (int t = 0; t < 4; t++) {
                cp16(buf + t * TILE32_B + soff[0], gsrc[t] + (kc + 2) * 32);
                cp16(buf + t * TILE32_B + soff[1], gsrc[t] + (kc + 2) * 32 + 8);
            }
            CP_COMMIT();
        }

        const uint32_t tb = smb + rbuf * STAGE32_B;
        #pragma unroll
        for (int ks = 0; ks < 2; ks++) {
            uint32_t ah[2][4], al[2][4];
            #pragma unroll
            for (int mm = 0; mm < 2; mm++) {
                uint32_t ad = sw64(arow + mm * 16, ks * 2 + agsel);
                ldm4(ah[mm], tb + ad);
                ldm4(al[mm], tb + TILE32_B + ad);
            }
            #pragma unroll
            for (int j = 0; j < 4; j++) {
                uint32_t bd = sw64(brow + j * 16, ks * 2 + bgsel);
                uint32_t bh[4], bl[4];
                ldm4(bh, tb + 2 * TILE32_B + bd);
                ldm4(bl, tb + 3 * TILE32_B + bd);
                mma16816(acc[0][2 * j],     ah[0], bh[0], bh[1]);
                mma16816(acc[0][2 * j + 1], ah[0], bh[2], bh[3]);
                mma16816(acc[1][2 * j],     ah[1], bh[0], bh[1]);
                mma16816(acc[1][2 * j + 1], ah[1], bh[2], bh[3]);
                mma16816(acc[0][2 * j],     al[0], bh[0], bh[1]);
                mma16816(acc[0][2 * j + 1], al[0], bh[2], bh[3]);
                mma16816(acc[1][2 * j],     al[1], bh[0], bh[1]);
                mma16816(acc[1][2 * j + 1], al[1], bh[2], bh[3]);
                mma16816(acc[0][2 * j],     ah[0], bl[0], bl[1]);
                mma16816(acc[0][2 * j + 1], ah[0], bl[2], bl[3]);
                mma16816(acc[1][2 * j],     ah[1], bl[0], bl[1]);
                mma16816(acc[1][2 * j + 1], ah[1], bl[2], bl[3]);
            }
        }
        rbuf = (rbuf == 2) ? 0 : rbuf + 1;
        wbuf = (wbuf == 2) ? 0 : wbuf + 1;
    }

    #pragma unroll
    for (int mm = 0; mm < 2; mm++) {
        #pragma unroll
        for (int half = 0; half < 2; half++) {
            const int r = wm * 32 + mm * 16 + (lane >> 2) + half * 8;
            const int m = m0 + r;
            float* rowp;
            if (MODE == 0) {
                const int s = blockIdx.y >> 4, n = blockIdx.y & 15;
                const int b = m >> 11, t = m & (Tt - 1);
                rowp = g_qkv + ((size_t)s * Bx * Nn + (size_t)(b * Nn + n)) * Tt * Hh
                             + (size_t)t * Hh;
            } else {
                rowp = outg + (size_t)m * Dd + blockIdx.y * 128;
            }
            #pragma unroll
            for (int j = 0; j < 8; j++) {
                const int c = wn * 64 + j * 8 + (lane & 3) * 2;
                float2 v;
                v.x = acc[mm][j][half * 2];
                v.y = acc[mm][j][half * 2 + 1];
                *(float2*)(rowp + c) = v;
            }
        }
    }
}

// ---------------------------------------------------------------------------
// RoPE + bf16 split of q (scaled) and k
// ---------------------------------------------------------------------------
__global__ void rope_split_kernel(const int* __restrict__ segment_pos)
{
    const int row = blockIdx.x * 4 + (threadIdx.x >> 6);
    const int h = threadIdx.x & 63;
    const int b = row / (Nn * Tt);
    const int nt = row - b * (Nn * Tt);
    const int n = nt >> 11;
    const int t = nt & (Tt - 1);
    const int pos = segment_pos[b * Tt + t];

    const double ts = pow(10000.0, (double)h / 64.0);
    const float ang = (float)((double)pos / ts);
    float sn, cs;
    sincosf(ang, &sn, &cs);

    const size_t base = ((size_t)(b * Nn + n) * Tt + t) * Hh;
    const float* q = g_qkv + base;
    const float* k = g_qkv + SZQ + base;
    const float qs = 0.08838834764831845f;

    float q1 = q[h], q2 = q[h + 64];
    float qa = (q1 * cs - q2 * sn) * qs;
    float qb = (q2 * cs + q1 * sn) * qs;
    float k1 = k[h], k2 = k[h + 64];
    float ka = k1 * cs - k2 * sn;
    float kb = k2 * cs + k1 * sn;

    __nv_bfloat16 hqa = __float2bfloat16(qa), hqb = __float2bfloat16(qb);
    __nv_bfloat16 hka = __float2bfloat16(ka), hkb = __float2bfloat16(kb);
    g_qh[base + h] = hqa;       g_qh[base + h + 64] = hqb;
    g_ql[base + h] = __float2bfloat16(qa - __bfloat162float(hqa));
    g_ql[base + h + 64] = __float2bfloat16(qb - __bfloat162float(hqb));
    g_kh[base + h] = hka;       g_kh[base + h + 64] = hkb;
    g_kl[base + h] = __float2bfloat16(ka - __bfloat162float(hka));
    g_kl[base + h + 64] = __float2bfloat16(kb - __bfloat162float(hkb));
}

// ---------------------------------------------------------------------------
// V: fp32 [b][n][t][h] -> bf16 hi/lo transposed [b][n][h][t]
// ---------------------------------------------------------------------------
__global__ void vsplit_kernel()
{
    __shared__ float tile[32][33];
    const int bnz = blockIdx.z;
    const int t0 = blockIdx.x * 32, h0 = blockIdx.y * 32;
    const float* v = g_qkv + 2 * SZQ + (size_t)bnz * Tt * Hh;
    #pragma unroll
    for (int i = threadIdx.y; i < 32; i += 8)
        tile[i][threadIdx.x] = v[(size_t)(t0 + i) * Hh + h0 + threadIdx.x];
    __syncthreads();
    const size_t dbase = (size_t)bnz * Hh * Tt;
    #pragma unroll
    for (int i = threadIdx.y; i < 32; i += 8) {
        float val = tile[threadIdx.x][i];
        __nv_bfloat16 hi = __float2bfloat16(val);
        size_t o = dbase + (size_t)(h0 + i) * Tt + t0 + threadIdx.x;
        g_vth[o] = hi;
        g_vtl[o] = __float2bfloat16(val - __bfloat162float(hi));
    }
}

// ---------------------------------------------------------------------------
// Flash attention: 128q x 64key chunks, Q in registers, 3-stage cp.async ring,
// fixed-base softmax fused into the PV kt-loop. LPT 1D grid.
// ---------------------------------------------------------------------------
#define AT_STAGE 65536
#define ATTN_SMEM2 (3 * 65536)   // 196608

__global__ void __launch_bounds__(256, 1) attn_mma_kernel()
{
    extern __shared__ char smc[];
    const uint32_t smb = smem_u32(smc);
    const int tid = threadIdx.x;
    const int wid = tid >> 5, lane = tid & 31;
    const int qt = 15 - (blockIdx.x >> 5);
    const int sub = blockIdx.x & 31;
    const int n = sub >> 1, b = sub & 1;
    const int t0 = qt * 128;
    const size_t bn = (size_t)(b * Nn + n) * Tt * Hh;

    const __nv_bfloat16* qhp = g_qh + bn;
    const __nv_bfloat16* qlp = g_ql + bn;
    const __nv_bfloat16* khp = g_kh + bn;
    const __nv_bfloat16* klp = g_kl + bn;
    const __nv_bfloat16* vhp = g_vth + bn;
    const __nv_bfloat16* vlp = g_vtl + bn;

    const int c_lo = (t0 >= WINDOW) ? ((t0 - WINDOW + 1) >> 6) : 0;
    const int c_hi = (t0 + 127) >> 6;

    const int arow = wid * 16 + (lane & 15);
    const int agsel = lane >> 4;
    const int bro = (lane & 7) + ((lane >> 4) << 3);
    const int bgsel = (lane >> 3) & 1;
    const int qr0 = t0 + wid * 16 + (lane >> 2);

    // ---- load Q into registers via one-time smem staging in buffer 0
    uint32_t qhf[8][4], qlf[8][4];
    {
        const int r = tid >> 1;
        const __nv_bfloat16* sh = qhp + (size_t)(t0 + r) * Hh;
        const __nv_bfloat16* sl = qlp + (size_t)(t0 + r) * Hh;
        #pragma unroll
        for (int i = 0; i < 8; i++) {
            int g = (tid & 1) * 8 + i;
            uint32_t off = (uint32_t)(r * 256 + ((g ^ (r & 7)) << 4));
            cp16(smb + off, sh + g * 8);
            cp16(smb + 32768 + off, sl + g * 8);
        }
        CP_COMMIT();
        asm volatile("cp.async.wait_group 0;" ::: "memory");
        __syncthreads();
        #pragma unroll
        for (int ks = 0; ks < 8; ks++) {
            uint32_t qa = (uint32_t)(arow * 256 + (((ks * 2 + agsel) ^ (arow & 7)) << 4));
            ldm4(qhf[ks], smb + qa);
            ldm4(qlf[ks], smb + 32768 + qa);
        }
        __syncthreads();  // all warps done reading buf0 before prologue overwrites
    }

    // ---- prologue: stage chunks c_lo, c_lo+1 into buffers 0, 1
    #pragma unroll 1
    for (int pc = 0; pc < 2; pc++) {
        const int c = c_lo + pc;
        const int k0 = c * 64;
        uint32_t sb = smb + pc * AT_STAGE;
        {
            const int r = tid >> 2;
            const __nv_bfloat16* sh = khp + (size_t)(k0 + r) * Hh;
            const __nv_bfloat16* sl = klp + (size_t)(k0 + r) * Hh;
            #pragma unroll
            for (int i = 0; i < 4; i++) {
                int g = (tid & 3) * 4 + i;
                uint32_t off = (uint32_t)(r * 256 + ((g ^ (r & 7)) << 4));
                cp16(sb + off, sh + g * 8);
                cp16(sb + 16384 + off, sl + g * 8);
            }
        }
        {
            const int r = tid >> 1;
            const __nv_bfloat16* sh = vhp + (size_t)r * Tt + k0;
            const __nv_bfloat16* sl = vlp + (size_t)r * Tt + k0;
            #pragma unroll
            for (int i = 0; i < 4; i++) {
                int g = (tid & 1) * 4 + i;
                uint32_t off = (uint32_t)(r * 128 + ((g ^ (r & 7)) << 4));
                cp16(sb + 32768 + off, sh + g * 8);
                cp16(sb + 49152 + off, sl + g * 8);
            }
        }
        CP_COMMIT();
    }

    float oacc[16][4];
    #pragma unroll
    for (int i = 0; i < 16; i++)
        #pragma unroll
        for (int q = 0; q < 4; q++) oacc[i][q] = 0.f;
    float l0 = 0.f, l1 = 0.f;

    int rbuf = 0, wbuf = 2;
    for (int c = c_lo; c <= c_hi; c++) {
        if (c < c_hi) asm volatile("cp.async.wait_group 1;" ::: "memory");
        else          asm volatile("cp.async.wait_group 0;" ::: "memory");
        __syncthreads();

        // prefetch chunk c+2 into the free buffer (freed at end of iter c-1)
        if (c + 2 <= c_hi) {
            const int k2 = (c + 2) * 64;
            uint32_t sb = smb + wbuf * AT_STAGE;
            {
                const int r = tid >> 2;
                const __nv_bfloat16* sh = khp + (size_t)(k2 + r) * Hh;
                const __nv_bfloat16* sl = klp + (size_t)(k2 + r) * Hh;
                #pragma unroll
                for (int i = 0; i < 4; i++) {
                    int g = (tid & 3) * 4 + i;
                    uint32_t off = (uint32_t)(r * 256 + ((g ^ (r & 7)) << 4));
                    cp16(sb + off, sh + g * 8);
                    cp16(sb + 16384 + off, sl + g * 8);
                }
            }
            {
                const int r = tid >> 1;
                const __nv_bfloat16* sh = vhp + (size_t)r * Tt + k2;
                const __nv_bfloat16* sl = vlp + (size_t)r * Tt + k2;
                #pragma unroll
                for (int i = 0; i < 4; i++) {
                    int g = (tid & 1) * 4 + i;
                    uint32_t off = (uint32_t)(r * 128 + ((g ^ (r & 7)) << 4));
                    cp16(sb + 32768 + off, sh + g * 8);
                    cp16(sb + 49152 + off, sl + g * 8);
                }
            }
            CP_COMMIT();
        }

        const int k0 = c * 64;
        const bool full = (k0 <= t0 - 64) && (k0 >= t0 - (WINDOW - 128));
        const uint32_t KHb = smb + rbuf * AT_STAGE;
        const uint32_t KLb = KHb + 16384, VHb = KHb + 32768, VLb = KHb + 49152;

        // ---- S = Q K^T (Q from registers)
        float sacc[8][4];
        #pragma unroll
        for (int i = 0; i < 8; i++)
            #pragma unroll
            for (int q = 0; q < 4; q++) sacc[i][q] = 0.f;

        #pragma unroll
        for (int ks = 0; ks < 8; ks++) {
            #pragma unroll
            for (int nk = 0; nk < 4; nk++) {
                int r = nk * 16 + bro;
                uint32_t ka = (uint32_t)(r * 256 + (((ks * 2 + bgsel) ^ (r & 7)) << 4));
                uint32_t khf[4], klf[4];
                ldm4(khf, KHb + ka);
                ldm4(klf, KLb + ka);
                mma16816(sacc[2 * nk],     qhf[ks], khf[0], khf[1]);
                mma16816(sacc[2 * nk + 1], qhf[ks], khf[2], khf[3]);
                mma16816(sacc[2 * nk],     qlf[ks], khf[0], khf[1]);
                mma16816(sacc[2 * nk + 1], qlf[ks], khf[2], khf[3]);
                mma16816(sacc[2 * nk],     qhf[ks], klf[0], klf[1]);
                mma16816(sacc[2 * nk + 1], qhf[ks], klf[2], klf[3]);
            }
        }

        // ---- fused: per 16-key group, softcap+exp+mask -> pack -> PV
        float s0 = 0.f, s1 = 0.f;
        #pragma unroll
        for (int kt = 0; kt < 4; kt++) {
            #pragma unroll
            for (int sub2 = 0; sub2 < 2; sub2++) {
                int nt = 2 * kt + sub2;
                #pragma unroll
                for (int q = 0; q < 4; q++) {
                    float s = sacc[nt][q];
                    float e = __expf(s * (2.0f / SOFT_CAP));
                    float r = __fdividef(2.0f, e + 1.0f);
                    float p = __expf(SOFT_CAP - SOFT_CAP * r);
                    if (!full) {
                        int qr = qr0 + ((q & 2) ? 8 : 0);
                        int kc = k0 + nt * 8 + (lane & 3) * 2 + (q & 1);
                        if (kc > qr || qr - kc >= WINDOW) p = 0.f;
                    }
                    sacc[nt][q] = p;
                    if (q & 2) s1 += p; else s0 += p;
                }
            }
            uint32_t phi[4], plo[4];
            #pragma unroll
            for (int part = 0; part < 4; part++) {
                int nt = 2 * kt + (part >> 1);
                float x = sacc[nt][(part & 1) * 2];
                float y = sacc[nt][(part & 1) * 2 + 1];
                __nv_bfloat162 h2 = __floats2bfloat162_rn(x, y);
                float lx = x - __bfloat162float(h2.x);
                float ly = y - __bfloat162float(h2.y);
                __nv_bfloat162 l2 = __floats2bfloat162_rn(lx, ly);
                phi[part] = *(uint32_t*)&h2;
                plo[part] = *(uint32_t*)&l2;
            }
            #pragma unroll
            for (int nh = 0; nh < 8; nh++) {
                int r = nh * 16 + bro;
                uint32_t va = (uint32_t)(r * 128 + (((kt * 2 + bgsel) ^ (r & 7)) << 4));
                uint32_t vhf[4], vlf[4];
                ldm4(vhf, VHb + va);
                ldm4(vlf, VLb + va);
                mma16816(oacc[2 * nh],     phi, vhf[0], vhf[1]);
                mma16816(oacc[2 * nh + 1], phi, vhf[2], vhf[3]);
                mma16816(oacc[2 * nh],     plo, vhf[0], vhf[1]);
                mma16816(oacc[2 * nh + 1], plo, vhf[2], vhf[3]);
                mma16816(oacc[2 * nh],     phi, vlf[0], vlf[1]);
                mma16816(oacc[2 * nh + 1], phi, vlf[2], vlf[3]);
            }
        }
        s0 += __shfl_xor_sync(0xffffffffu, s0, 1);
        s0 += __shfl_xor_sync(0xffffffffu, s0, 2);
        s1 += __shfl_xor_sync(0xffffffffu, s1, 1);
        s1 += __shfl_xor_sync(0xffffffffu, s1, 2);
        l0 += s0;
        l1 += s1;

        __syncthreads();  // all warps done reading rbuf before it becomes wbuf target
        rbuf = (rbuf == 2) ? 0 : rbuf + 1;
        wbuf = (wbuf == 2) ? 0 : wbuf + 1;
    }

    // normalize + hi/lo split + write enc directly as bf16 pair arrays
    float inv0 = __fdividef(1.f, l0), inv1 = __fdividef(1.f, l1);
    const int tr0 = t0 + wid * 16 + (lane >> 2);
    #pragma unroll
    for (int nt = 0; nt < 16; nt++) {
        int col = nt * 8 + (lane & 3) * 2;
        size_t o0 = ((size_t)b * Tt + tr0) * Dd + n * Hh + col;
        size_t o1 = ((size_t)b * Tt + tr0 + 8) * Dd + n * Hh + col;
        float x0 = oacc[nt][0] * inv0, y0 = oacc[nt][1] * inv0;
        float x1 = oacc[nt][2] * inv1, y1 = oacc[nt][3] * inv1;
        __nv_bfloat162 h0 = __floats2bfloat162_rn(x0, y0);
        __nv_bfloat162 h1 = __floats2bfloat162_rn(x1, y1);
        __nv_bfloat162 l0v = __floats2bfloat162_rn(x0 - __bfloat162float(h0.x),
                                                   y0 - __bfloat162float(h0.y));
        __nv_bfloat162 l1v = __floats2bfloat162_rn(x1 - __bfloat162float(h1.x),
                                                   y1 - __bfloat162float(h1.y));
        *(__nv_bfloat162*)(g_ehi + o0) = h0;
        *(__nv_bfloat162*)(g_elo + o0) = l0v;
        *(__nv_bfloat162*)(g_ehi + o1) = h1;
        *(__nv_bfloat162*)(g_elo + o1) = l1v;
    }
}

// ---------------------------------------------------------------------------
extern "C" void kernel_launch(void* const* d_in, const int* in_sizes, int n_in,
                              void* d_out, int out_size)
{
    const float* x       = (const float*)d_in[0];
    const float* w_qkv   = (const float*)d_in[1];
    const float* w_out   = (const float*)d_in[2];
    const int*   seg_pos = (const int*)d_in[3];
    float* out = (float*)d_out;

    const int n4 = Bx * Tt * Dd / 4;

    split_x_kernel<<<n4 / 256, 256>>>(x);
    transpose_split_kernel<0><<<dim3(Hh / 32, Dd / 32, 48), dim3(32, 8)>>>(w_qkv, Dd, Hh);
    transpose_split_kernel<1><<<dim3(Dd / 32, Dd / 32, 1), dim3(32, 8)>>>(w_out, Dd, Dd);

    cudaFuncSetAttribute(mma_gemm<0>, cudaFuncAttributeMaxDynamicSharedMemorySize, GEMM_SMEM);
    cudaFuncSetAttribute(mma_gemm<1>, cudaFuncAttributeMaxDynamicSharedMemorySize, GEMM_SMEM);
    cudaFuncSetAttribute(attn_mma_kernel, cudaFuncAttributeMaxDynamicSharedMemorySize, ATTN_SMEM2);

    mma_gemm<0><<<dim3(Bx * Tt / 128, 48), 256, GEMM_SMEM>>>(nullptr);
    rope_split_kernel<<<dim3(Bx * Nn * Tt / 4), 256>>>(seg_pos);
    vsplit_kernel<<<dim3(Tt / 32, Hh / 32, Bx * Nn), dim3(32, 8)>>>();

    attn_mma_kernel<<<dim3(16 * Nn * Bx), 256, ATTN_SMEM2>>>();

    mma_gemm<1><<<dim3(Bx * Tt / 128, Dd / 128), 256, GEMM_SMEM>>>(out);
}